// round 3
// baseline (speedup 1.0000x reference)
#include <cuda_runtime.h>
#include <stdint.h>

#define BB   16
#define CH   3
#define HH   1024
#define WW   1024
#define NCRACK 8
#define PIX    (HH * WW)
#define CRACK_VAL 0.05f

// ---------------------------------------------------------------------------
// Single fused kernel.
// Grid: (HH rows, CH, BB); block: 256 threads, each handling one float4
// (4 pixels) of one image row. The crack mask for a given row is computed
// analytically: each of the 8 lines of batch b covers a contiguous x-interval
// at row y (closed-form inversion of the reference Bresenham recurrence):
//
//   x-major (dx >= dy), minor count m = sy*(y - y0), valid for 0 <= m <= dy:
//     m == 0 : t in [0, floor(dx/(2dy))]            (dy==0: t in [0, dx])
//     m >= 1 : t in [floor(dx(2m-1)/(2dy))+1, floor(dx(2m+1)/(2dy))]
//     clamped to t <= dx;  x = x0 + sx*t  -> contiguous interval.
//
//   y-major (dy > dx), t = sy*(y - y0), valid 0 <= t <= dy:
//     k = max(0, ceil((2*t*dx - dy)/(2*dy)));  single pixel x = x0 + sx*k.
//
// These match the reference scan exactly (k(t) form validated rel_err=0).
// ---------------------------------------------------------------------------
__global__ __launch_bounds__(256) void fused_crack_kernel(
    const float4* __restrict__ x, float4* __restrict__ out,
    const int* __restrict__ ep)
{
    __shared__ int2 iv[NCRACK];          // per-line [xlo, xhi] at this row

    const unsigned row = blockIdx.x;     // y
    const unsigned c   = blockIdx.y;
    const unsigned b   = blockIdx.z;

    if (threadIdx.x < NCRACK) {
        const int* e = ep + (b * NCRACK + threadIdx.x) * 4;  // (y0,x0,y1,x1)
        int y0 = e[0], x0 = e[1], y1 = e[2], x1 = e[3];
        int dx = abs(x1 - x0);
        int dy = abs(y1 - y0);
        int sx = (x0 < x1) ? 1 : -1;
        int sy = (y0 < y1) ? 1 : -1;
        int y  = (int)row;

        int xlo = 1, xhi = 0;            // empty interval
        if (dx >= dy) {
            int m = sy * (y - y0);
            if (m >= 0 && m <= dy) {
                int tlo, thi;
                if (dy == 0)      { tlo = 0; thi = dx; }
                else if (m == 0)  { tlo = 0; thi = dx / (2 * dy); }
                else {
                    tlo = (dx * (2 * m - 1)) / (2 * dy) + 1;
                    thi = (dx * (2 * m + 1)) / (2 * dy);
                }
                thi = min(thi, dx);
                int xa = x0 + sx * tlo;
                int xb = x0 + sx * thi;
                xlo = min(xa, xb);
                xhi = max(xa, xb);
            }
        } else {
            int t = sy * (y - y0);
            if (t >= 0 && t <= dy) {
                int a  = 2 * t * dx - dy;
                int b2 = 2 * dy;
                int k  = max(0, (a + b2 - 1) / b2);   // clamped ceil (validated)
                xlo = xhi = x0 + sx * k;
            }
        }
        iv[threadIdx.x] = make_int2(xlo, xhi);
    }
    __syncthreads();

    const unsigned p4  = row * 256u + threadIdx.x;            // float4 index in image
    const unsigned idx = (b * CH + c) * (PIX / 4) + p4;
    const int xb0 = (int)(threadIdx.x * 4u);                  // first x of this thread

    unsigned m = 0;
    #pragma unroll
    for (int i = 0; i < NCRACK; i++) {
        int lo = iv[i].x, hi = iv[i].y;
        m |= ((xb0     >= lo && xb0     <= hi) ? 1u : 0u)
           | ((xb0 + 1 >= lo && xb0 + 1 <= hi) ? 2u : 0u)
           | ((xb0 + 2 >= lo && xb0 + 2 <= hi) ? 4u : 0u)
           | ((xb0 + 3 >= lo && xb0 + 3 <= hi) ? 8u : 0u);
    }

    float4 v = x[idx];
    float4 r;
    r.x = (m & 1u) ? CRACK_VAL : fminf(fmaxf(v.x, 0.0f), 1.0f);
    r.y = (m & 2u) ? CRACK_VAL : fminf(fmaxf(v.y, 0.0f), 1.0f);
    r.z = (m & 4u) ? CRACK_VAL : fminf(fmaxf(v.z, 0.0f), 1.0f);
    r.w = (m & 8u) ? CRACK_VAL : fminf(fmaxf(v.w, 0.0f), 1.0f);
    out[idx] = r;
}

// ---------------------------------------------------------------------------
extern "C" void kernel_launch(void* const* d_in, const int* in_sizes, int n_in,
                              void* d_out, int out_size) {
    const float* x   = (const float*)d_in[0];   // [16,3,1024,1024] f32
    const int*   ep  = (const int*)d_in[1];     // [16,8,4] i32
    float*       out = (float*)d_out;

    dim3 grid(HH, CH, BB);                       // one block per (row, channel, batch)
    fused_crack_kernel<<<grid, 256>>>((const float4*)x, (float4*)out, ep);
}

// round 4
// speedup vs baseline: 1.7997x; 1.7997x over previous
#include <cuda_runtime.h>
#include <stdint.h>

#define BB   16
#define CH   3
#define HH   1024
#define WW   1024
#define NCRACK 8
#define PIX    (HH * WW)
#define CRACK_VAL 0.05f

// ---------------------------------------------------------------------------
// Single fused kernel, one block per (row, batch), covering all 3 channels.
//
// Prologue (per block):
//   - threads 0..7: closed-form x-interval of line i at row y (validated
//     rel_err=0 in R2/R3):
//       x-major (dx>=dy), m = sy*(y-y0) in [0,dy]:
//         m==0: t in [0, floor(dx/(2dy))] (dy==0: [0,dx])
//         m>=1: t in [floor(dx(2m-1)/(2dy))+1, floor(dx(2m+1)/(2dy))]
//       clamped to t<=dx; x = x0 + sx*t.
//       y-major: single pixel x = x0 + sx*max(0,ceil((2t*dx-dy)/(2dy))).
//   - threads 0..31: build 1024-bit row mask (32 words) from the 8 intervals.
//
// Hot loop (per thread): read 4-bit mask from smem, then for each of the 3
// channels: float4 load -> select(crack, clamp) -> float4 store.
// ---------------------------------------------------------------------------
__global__ __launch_bounds__(256) void fused_crack_kernel(
    const float4* __restrict__ x, float4* __restrict__ out,
    const int* __restrict__ ep)
{
    __shared__ int2     iv[NCRACK];      // per-line [xlo, xhi] at this row
    __shared__ unsigned rowmask[32];     // 1024-bit mask for this row

    const unsigned row = blockIdx.x;     // y
    const unsigned b   = blockIdx.y;

    if (threadIdx.x < NCRACK) {
        const int* e = ep + (b * NCRACK + threadIdx.x) * 4;  // (y0,x0,y1,x1)
        int y0 = e[0], x0 = e[1], y1 = e[2], x1 = e[3];
        int dx = abs(x1 - x0);
        int dy = abs(y1 - y0);
        int sx = (x0 < x1) ? 1 : -1;
        int sy = (y0 < y1) ? 1 : -1;
        int y  = (int)row;

        int xlo = 1, xhi = 0;            // empty
        if (dx >= dy) {
            int m = sy * (y - y0);
            if (m >= 0 && m <= dy) {
                int tlo, thi;
                if (dy == 0)      { tlo = 0; thi = dx; }
                else if (m == 0)  { tlo = 0; thi = dx / (2 * dy); }
                else {
                    tlo = (dx * (2 * m - 1)) / (2 * dy) + 1;
                    thi = (dx * (2 * m + 1)) / (2 * dy);
                }
                thi = min(thi, dx);
                int xa = x0 + sx * tlo;
                int xb = x0 + sx * thi;
                xlo = min(xa, xb);
                xhi = max(xa, xb);
            }
        } else {
            int t = sy * (y - y0);
            if (t >= 0 && t <= dy) {
                int a  = 2 * t * dx - dy;
                int b2 = 2 * dy;
                int k  = max(0, (a + b2 - 1) / b2);
                xlo = xhi = x0 + sx * k;
            }
        }
        iv[threadIdx.x] = make_int2(xlo, xhi);
    }
    __syncthreads();

    if (threadIdx.x < 32) {
        int base = (int)(threadIdx.x * 32u);
        unsigned w = 0;
        #pragma unroll
        for (int i = 0; i < NCRACK; i++) {
            int lo = max(iv[i].x - base, 0);
            int hi = min(iv[i].y - base, 31);
            if (lo <= hi) {
                int len = hi - lo + 1;
                w |= (0xFFFFFFFFu >> (32 - len)) << lo;
            }
        }
        rowmask[threadIdx.x] = w;
    }
    __syncthreads();

    // 4-bit mask for this thread's 4 pixels
    const unsigned m = (rowmask[threadIdx.x >> 3] >> ((threadIdx.x & 7u) * 4u)) & 0xFu;

    const unsigned p4 = row * 256u + threadIdx.x;             // float4 index in image
    const unsigned base = b * CH * (PIX / 4) + p4;

    float4 v0 = x[base];
    float4 v1 = x[base +     (PIX / 4)];
    float4 v2 = x[base + 2 * (PIX / 4)];

    #define APPLY(v) do { \
        (v).x = (m & 1u) ? CRACK_VAL : fminf(fmaxf((v).x, 0.0f), 1.0f); \
        (v).y = (m & 2u) ? CRACK_VAL : fminf(fmaxf((v).y, 0.0f), 1.0f); \
        (v).z = (m & 4u) ? CRACK_VAL : fminf(fmaxf((v).z, 0.0f), 1.0f); \
        (v).w = (m & 8u) ? CRACK_VAL : fminf(fmaxf((v).w, 0.0f), 1.0f); \
    } while (0)

    APPLY(v0); APPLY(v1); APPLY(v2);

    out[base]                 = v0;
    out[base +     (PIX / 4)] = v1;
    out[base + 2 * (PIX / 4)] = v2;
}

// ---------------------------------------------------------------------------
extern "C" void kernel_launch(void* const* d_in, const int* in_sizes, int n_in,
                              void* d_out, int out_size) {
    const float* x   = (const float*)d_in[0];   // [16,3,1024,1024] f32
    const int*   ep  = (const int*)d_in[1];     // [16,8,4] i32
    float*       out = (float*)d_out;

    dim3 grid(HH, BB);                           // one block per (row, batch)
    fused_crack_kernel<<<grid, 256>>>((const float4*)x, (float4*)out, ep);
}